// round 15
// baseline (speedup 1.0000x reference)
#include <cuda_runtime.h>
#include <math.h>

#define FEAT 44
#define TED 84
#define HALF_TED 42
#define DIN 128
#define H0 64
#define H1 32
#define MAXB 4096
#define GW 4
#define LN_SIGMA 3.2188758248682006f    /* ln(25) */
#define TWO_PI 6.28318530717958647692f

typedef unsigned long long u64;

__device__ float g_e0[MAXB * H0];
__device__ float g_invstd[MAXB];

__device__ __forceinline__ float swishf(float x) {
    return __fdividef(x, 1.0f + __expf(-x));
}

__device__ __forceinline__ u64 ffma2(u64 a, u64 b, u64 c) {
    u64 d;
    asm("fma.rn.f32x2 %0, %1, %2, %3;" : "=l"(d) : "l"(a), "l"(b), "l"(c));
    return d;
}
__device__ __forceinline__ u64 pack2(float lo, float hi) {
    u64 r;
    asm("mov.b64 %0, {%1, %2};" : "=l"(r) : "f"(lo), "f"(hi));
    return r;
}
__device__ __forceinline__ void unpack2(u64 v, float& lo, float& hi) {
    asm("mov.b64 {%0, %1}, %2;" : "=f"(lo), "=f"(hi) : "l"(v));
}

// ---------------------------------------------------------------------------
// k_graph: one warp per graph (4096 warps total).
// ---------------------------------------------------------------------------
__global__ __launch_bounds__(128) void k_graph(
    const float* __restrict__ t, const float* __restrict__ W_f,
    const float* __restrict__ ew, const float* __restrict__ eb,
    const float* __restrict__ w0, const float* __restrict__ b0, int B)
{
    __shared__ float s_ewT[TED * TED];
    __shared__ float s_w0t[TED * H0];
    __shared__ float s_wf[HALF_TED];
    __shared__ float s_eb[TED];
    __shared__ float s_b0[H0];
    __shared__ float s_temb[GW][TED];
    __shared__ float s_emb[GW][TED];

    int tid = threadIdx.x;
    int wid = tid >> 5, lane = tid & 31;

    for (int idx = tid; idx < TED * TED; idx += blockDim.x) {
        int o = idx / TED, i = idx - o * TED;
        s_ewT[i * TED + o] = ew[idx];
    }
    for (int idx = tid; idx < TED * H0; idx += blockDim.x) {
        int o = idx / TED, i = idx - o * TED;
        s_w0t[i * H0 + o] = w0[o * DIN + FEAT + i];
    }
    if (tid < HALF_TED) s_wf[tid] = W_f[tid];
    if (tid < TED)      s_eb[tid] = eb[tid];
    if (tid < H0)       s_b0[tid] = b0[tid];
    __syncthreads();

    int g = blockIdx.x * GW + wid;
    if (g >= B) return;

    float tg = __ldg(&t[g]);

    #pragma unroll
    for (int r = 0; r < 2; r++) {
        int idx = lane + 32 * r;
        if (idx < HALF_TED) {
            float s, c;
            sincosf(tg * s_wf[idx] * TWO_PI, &s, &c);
            s_temb[wid][idx] = s;
            s_temb[wid][idx + HALF_TED] = c;
        }
    }
    __syncwarp();

    #pragma unroll
    for (int r = 0; r < 3; r++) {
        int o = lane + 32 * r;
        if (o < TED) {
            float acc = s_eb[o];
            #pragma unroll 4
            for (int i = 0; i < TED; i++)
                acc = fmaf(s_temb[wid][i], s_ewT[i * TED + o], acc);
            s_emb[wid][o] = swishf(acc);
        }
    }
    __syncwarp();

    #pragma unroll
    for (int r = 0; r < 2; r++) {
        int o = lane + 32 * r;
        float acc = s_b0[o];
        #pragma unroll 4
        for (int i = 0; i < TED; i++)
            acc = fmaf(s_emb[wid][i], s_w0t[i * H0 + o], acc);
        g_e0[(size_t)g * H0 + o] = acc;
    }
    if (lane == 0) {
        float v = (expf(2.0f * tg * LN_SIGMA) - 1.0f) * (0.5f / LN_SIGMA);
        g_invstd[g] = rsqrtf(v);
    }
}

// ---------------------------------------------------------------------------
// k_main: 2 nodes/thread (weight LDS amortized), forced 3 CTAs/SM for
// latency hiding (R13: regs=212 -> occ 12%, issue 42% was the binder).
// e0 loads chunked as float4 (unroll 4 keeps lane select static).
// ---------------------------------------------------------------------------
__global__ __launch_bounds__(128, 3) void k_main(
    const float* __restrict__ node_attr, const int* __restrict__ ptr,
    const float* __restrict__ w0, const float* __restrict__ w1,
    const float* __restrict__ b1, const float* __restrict__ w2,
    const float* __restrict__ b2, float* __restrict__ out,
    int n, int B)
{
    __shared__ int s_ptr[MAXB + 1];
    __shared__ ulonglong2 s_w0v[H0 * 11];
    __shared__ ulonglong2 s_w1v[H0 * 8];
    __shared__ u64 s_w2p01[H1];
    __shared__ u64 s_w2p23[H1];

    int tid = threadIdx.x;
    for (int idx = tid; idx <= B; idx += 128) s_ptr[idx] = ptr[idx];
    for (int idx = tid; idx < H0 * 11; idx += 128) {
        int j = idx / 11, k4 = idx - j * 11;
        float4 v = *(const float4*)&w0[j * DIN + k4 * 4];
        ulonglong2 p;
        p.x = pack2(v.x, v.y);
        p.y = pack2(v.z, v.w);
        s_w0v[idx] = p;
    }
    for (int idx = tid; idx < H0 * 8; idx += 128) {
        int k = idx / 8, qq = idx - k * 8;
        ulonglong2 p;
        p.x = pack2(w1[(4 * qq + 0) * H0 + k], w1[(4 * qq + 1) * H0 + k]);
        p.y = pack2(w1[(4 * qq + 2) * H0 + k], w1[(4 * qq + 3) * H0 + k]);
        s_w1v[idx] = p;
    }
    if (tid < H1) {
        s_w2p01[tid] = pack2(w2[0 * H1 + tid], w2[1 * H1 + tid]);
        s_w2p23[tid] = pack2(w2[2 * H1 + tid], w2[3 * H1 + tid]);
    }
    __syncthreads();

    int node0 = (blockIdx.x * 128 + tid) * 2;
    if (node0 >= n) return;
    int node1 = node0 + 1;
    bool has1 = node1 < n;

    int lo = 0, hi = B;
    while (lo < hi) {
        int mid = (lo + hi + 1) >> 1;
        if (s_ptr[mid] <= node0) lo = mid; else hi = mid - 1;
    }
    int seg0 = lo;
    int seg1 = seg0;
    while (seg1 < B - 1 && s_ptr[seg1 + 1] <= node1) seg1++;

    u64 a2a[22], a2b[22];
    {
        const float4* ar0 = (const float4*)(node_attr + (size_t)node0 * FEAT);
        #pragma unroll
        for (int i = 0; i < 11; i++) {
            float4 v = __ldg(&ar0[i]);
            a2a[2 * i]     = pack2(v.x, v.y);
            a2a[2 * i + 1] = pack2(v.z, v.w);
        }
        const float4* ar1 = (const float4*)(node_attr + (size_t)node1 * FEAT);
        #pragma unroll
        for (int i = 0; i < 11; i++) {
            float4 v = has1 ? __ldg(&ar1[i]) : make_float4(0.f, 0.f, 0.f, 0.f);
            a2b[2 * i]     = pack2(v.x, v.y);
            a2b[2 * i + 1] = pack2(v.z, v.w);
        }
    }

    const float* e0a = g_e0 + (size_t)seg0 * H0;
    const float* e0b = g_e0 + (size_t)seg1 * H0;

    u64 acc1pa[16], acc1pb[16];
    const float2* b1p = (const float2*)b1;
    #pragma unroll
    for (int q = 0; q < 16; q++) {
        float2 v = __ldg(&b1p[q]);
        u64 pv = pack2(v.x, v.y);
        acc1pa[q] = pv;
        acc1pb[q] = pv;
    }

    float4 e0ca, e0cb;
    #pragma unroll 4
    for (int j = 0; j < H0; j++) {
        if ((j & 3) == 0) {
            e0ca = *(const float4*)(e0a + j);
            e0cb = *(const float4*)(e0b + j);
        }
        float ea = (j & 3) == 0 ? e0ca.x : (j & 3) == 1 ? e0ca.y : (j & 3) == 2 ? e0ca.z : e0ca.w;
        float eb = (j & 3) == 0 ? e0cb.x : (j & 3) == 1 ? e0cb.y : (j & 3) == 2 ? e0cb.z : e0cb.w;
        u64 acc2a = pack2(ea, 0.0f);
        u64 acc2b = pack2(eb, 0.0f);
        const ulonglong2* wr = &s_w0v[j * 11];
        #pragma unroll
        for (int k4 = 0; k4 < 11; k4++) {
            ulonglong2 w = wr[k4];
            acc2a = ffma2(w.x, a2a[2 * k4],     acc2a);
            acc2a = ffma2(w.y, a2a[2 * k4 + 1], acc2a);
            acc2b = ffma2(w.x, a2b[2 * k4],     acc2b);
            acc2b = ffma2(w.y, a2b[2 * k4 + 1], acc2b);
        }
        float alo, ahi, blo, bhi;
        unpack2(acc2a, alo, ahi);
        unpack2(acc2b, blo, bhi);
        float ha = swishf(alo + ahi);
        float hb = swishf(blo + bhi);

        u64 hha = pack2(ha, ha);
        u64 hhb = pack2(hb, hb);
        const ulonglong2* w1r = &s_w1v[j * 8];
        #pragma unroll
        for (int qq = 0; qq < 8; qq++) {
            ulonglong2 w = w1r[qq];
            acc1pa[2 * qq]     = ffma2(w.x, hha, acc1pa[2 * qq]);
            acc1pa[2 * qq + 1] = ffma2(w.y, hha, acc1pa[2 * qq + 1]);
            acc1pb[2 * qq]     = ffma2(w.x, hhb, acc1pb[2 * qq]);
            acc1pb[2 * qq + 1] = ffma2(w.y, hhb, acc1pb[2 * qq + 1]);
        }
    }

    float bb0 = __ldg(&b2[0]), bb1 = __ldg(&b2[1]);
    float bb2 = __ldg(&b2[2]), bb3 = __ldg(&b2[3]);
    u64 oa01 = pack2(bb0, bb1), oa23 = pack2(bb2, bb3);
    u64 ob01 = oa01, ob23 = oa23;
    #pragma unroll 4
    for (int q = 0; q < 16; q++) {
        u64 w01a = s_w2p01[2 * q],     w23a = s_w2p23[2 * q];
        u64 w01b = s_w2p01[2 * q + 1], w23b = s_w2p23[2 * q + 1];
        float x0, x1;
        unpack2(acc1pa[q], x0, x1);
        float h0 = swishf(x0), h1 = swishf(x1);
        u64 h00 = pack2(h0, h0), h11 = pack2(h1, h1);
        oa01 = ffma2(w01a, h00, oa01);
        oa23 = ffma2(w23a, h00, oa23);
        oa01 = ffma2(w01b, h11, oa01);
        oa23 = ffma2(w23b, h11, oa23);
        unpack2(acc1pb[q], x0, x1);
        h0 = swishf(x0); h1 = swishf(x1);
        h00 = pack2(h0, h0); h11 = pack2(h1, h1);
        ob01 = ffma2(w01a, h00, ob01);
        ob23 = ffma2(w23a, h00, ob23);
        ob01 = ffma2(w01b, h11, ob01);
        ob23 = ffma2(w23b, h11, ob23);
    }

    float o0, o1, o2, o3;
    float is0 = __ldg(&g_invstd[seg0]);
    unpack2(oa01, o0, o1);
    unpack2(oa23, o2, o3);
    float4 oA;
    oA.x = swishf(o0) * is0;
    oA.y = swishf(o1) * is0;
    oA.z = swishf(o2) * is0;
    oA.w = swishf(o3) * is0;
    *(float4*)(out + (size_t)node0 * 4) = oA;

    if (has1) {
        float is1 = __ldg(&g_invstd[seg1]);
        unpack2(ob01, o0, o1);
        unpack2(ob23, o2, o3);
        float4 oB;
        oB.x = swishf(o0) * is1;
        oB.y = swishf(o1) * is1;
        oB.z = swishf(o2) * is1;
        oB.w = swishf(o3) * is1;
        *(float4*)(out + (size_t)node1 * 4) = oB;
    }
}

// ---------------------------------------------------------------------------
extern "C" void kernel_launch(void* const* d_in, const int* in_sizes, int n_in,
                              void* d_out, int out_size)
{
    const float* node_attr = (const float*)d_in[0];
    const float* t   = (const float*)d_in[1];
    const int*   ptr = (const int*)d_in[2];
    const float* W_f = (const float*)d_in[3];
    const float* ew  = (const float*)d_in[4];
    const float* eb  = (const float*)d_in[5];
    const float* w0  = (const float*)d_in[6];
    const float* b0  = (const float*)d_in[7];
    const float* w1  = (const float*)d_in[8];
    const float* b1  = (const float*)d_in[9];
    const float* w2  = (const float*)d_in[10];
    const float* b2  = (const float*)d_in[11];
    float* out = (float*)d_out;

    int B = in_sizes[1];           // 4096
    int n = in_sizes[0] / FEAT;    // 1048576

    int gblocks = (B + GW - 1) / GW;               // 1024: one warp per graph
    k_graph<<<gblocks, 128>>>(t, W_f, ew, eb, w0, b0, B);
    int pairs = (n + 1) / 2;
    k_main<<<(pairs + 127) / 128, 128>>>(node_attr, ptr, w0, w1, b1, w2, b2, out, n, B);
}